// round 2
// baseline (speedup 1.0000x reference)
#include <cuda_runtime.h>
#include <cstdint>

// ---------------------------------------------------------------------------
// Problem constants
// ---------------------------------------------------------------------------
#define NN 50000
#define EE 800000
#define IN_CH 128
#define HID 64
#define HEADS 4
#define HC (HEADS * HID)   // 256
#define OUT_CH 64

// ---------------------------------------------------------------------------
// Scratch (device globals; no allocation allowed anywhere)
// ---------------------------------------------------------------------------
__device__ __align__(16) float g_h[(size_t)NN * HC];      // per-relation GEMM output
__device__ __align__(16) float g_out1[(size_t)NN * HC];   // layer1 accumulation
__device__ __align__(16) float g_out2[(size_t)NN * HID];  // layer2 accumulation
__device__ __align__(16) float g_als[(size_t)NN * HEADS];
__device__ __align__(16) float g_ald[(size_t)NN * HEADS];
__device__ __align__(16) float g_denom[(size_t)NN * HEADS];

// ---------------------------------------------------------------------------
// Helpers
// ---------------------------------------------------------------------------
__device__ __forceinline__ float lrelu(float x) { return fmaxf(x, 0.2f * x); }

__device__ __forceinline__ void red_add_v4(float* p, float4 v) {
    asm volatile("red.global.add.v4.f32 [%0], {%1, %2, %3, %4};"
                 :: "l"(p), "f"(v.x), "f"(v.y), "f"(v.z), "f"(v.w) : "memory");
}
__device__ __forceinline__ void red_add_v2(float* p, float2 v) {
    asm volatile("red.global.add.v2.f32 [%0], {%1, %2};"
                 :: "l"(p), "f"(v.x), "f"(v.y) : "memory");
}

// ---------------------------------------------------------------------------
// Tiled SGEMM: C[M,N] = op(A)[M,K] @ B[K,N] (+ bias). op = optional relu.
// ASEL: -1 = A from param, 1 = g_out1, 2 = g_out2
// CSEL: -1 = C from param, 0 = g_h
// ---------------------------------------------------------------------------
template<int BM, int BN, int BK, int TM, int TN, bool RELU_A, bool BIAS,
         int ASEL, int CSEL>
__global__ void sgemm_kernel(const float* __restrict__ Ap, const float* __restrict__ B,
                             float* __restrict__ Cp, const float* __restrict__ bias,
                             int M, int N, int K) {
    const float* A = (ASEL == 1) ? (const float*)g_out1
                   : (ASEL == 2) ? (const float*)g_out2 : Ap;
    float* C = (CSEL == 0) ? (float*)g_h : Cp;

    constexpr int NT = (BM / TM) * (BN / TN);
    __shared__ float As[BK][BM];
    __shared__ float Bs[BK][BN];
    const int tid = threadIdx.x;
    const int block_row = blockIdx.y * BM;
    const int block_col = blockIdx.x * BN;
    const int tcol = tid % (BN / TN);
    const int trow = tid / (BN / TN);

    float acc[TM][TN];
#pragma unroll
    for (int i = 0; i < TM; i++)
#pragma unroll
        for (int j = 0; j < TN; j++) acc[i][j] = 0.f;

    for (int k0 = 0; k0 < K; k0 += BK) {
        // A tile: BM x BK (float4 along K), stored transposed in smem
#pragma unroll
        for (int i = tid; i < BM * BK / 4; i += NT) {
            int r  = i / (BK / 4);
            int c4 = i % (BK / 4);
            int gr = block_row + r;
            float4 v = make_float4(0.f, 0.f, 0.f, 0.f);
            if (gr < M) v = *(const float4*)(A + (size_t)gr * K + k0 + c4 * 4);
            if (RELU_A) {
                v.x = fmaxf(v.x, 0.f); v.y = fmaxf(v.y, 0.f);
                v.z = fmaxf(v.z, 0.f); v.w = fmaxf(v.w, 0.f);
            }
            As[c4 * 4 + 0][r] = v.x; As[c4 * 4 + 1][r] = v.y;
            As[c4 * 4 + 2][r] = v.z; As[c4 * 4 + 3][r] = v.w;
        }
        // B tile: BK x BN
#pragma unroll
        for (int i = tid; i < BK * BN / 4; i += NT) {
            int r  = i / (BN / 4);
            int c4 = i % (BN / 4);
            float4 v = *(const float4*)(B + (size_t)(k0 + r) * N + block_col + c4 * 4);
            *(float4*)&Bs[r][c4 * 4] = v;
        }
        __syncthreads();
#pragma unroll
        for (int kk = 0; kk < BK; kk++) {
            float ar[TM], br[TN];
#pragma unroll
            for (int i = 0; i < TM; i++) ar[i] = As[kk][trow * TM + i];
#pragma unroll
            for (int j = 0; j < TN; j++) br[j] = Bs[kk][tcol * TN + j];
#pragma unroll
            for (int i = 0; i < TM; i++)
#pragma unroll
                for (int j = 0; j < TN; j++) acc[i][j] += ar[i] * br[j];
        }
        __syncthreads();
    }
#pragma unroll
    for (int i = 0; i < TM; i++) {
        int gr = block_row + trow * TM + i;
        if (gr >= M) continue;
#pragma unroll
        for (int j = 0; j < TN; j += 4) {
            int gc = block_col + tcol * TN + j;
            float4 v = make_float4(acc[i][j], acc[i][j + 1], acc[i][j + 2], acc[i][j + 3]);
            if (BIAS) {
                v.x += bias[gc]; v.y += bias[gc + 1];
                v.z += bias[gc + 2]; v.w += bias[gc + 3];
            }
            *(float4*)(C + (size_t)gr * N + gc) = v;
        }
    }
}

// ---------------------------------------------------------------------------
// Attention coefficients: als[n,h] = <g_h[n,h,:], a_s[h,:]>, same for ald.
// One warp per node; 8 lanes per head, 8 channels per lane.
// Also zeroes g_denom for this node (replaces a memset node).
// ---------------------------------------------------------------------------
__global__ void attn_coef_kernel(const float* __restrict__ a_s,
                                 const float* __restrict__ a_d,
                                 int N) {
    int warp = (blockIdx.x * blockDim.x + threadIdx.x) >> 5;
    int lane = threadIdx.x & 31;
    if (warp >= N) return;
    int head = lane >> 3;
    int coff = head * HID + (lane & 7) * 8;
    const float4* hp = (const float4*)(g_h + (size_t)warp * HC + coff);
    const float4* sp = (const float4*)(a_s + coff);
    const float4* dp = (const float4*)(a_d + coff);
    float4 h0 = hp[0], h1 = hp[1];
    float4 s0 = sp[0], s1 = sp[1];
    float4 d0 = dp[0], d1 = dp[1];
    float ps = h0.x * s0.x + h0.y * s0.y + h0.z * s0.z + h0.w * s0.w
             + h1.x * s1.x + h1.y * s1.y + h1.z * s1.z + h1.w * s1.w;
    float pd = h0.x * d0.x + h0.y * d0.y + h0.z * d0.z + h0.w * d0.w
             + h1.x * d1.x + h1.y * d1.y + h1.z * d1.z + h1.w * d1.w;
#pragma unroll
    for (int off = 4; off; off >>= 1) {
        ps += __shfl_down_sync(0xffffffffu, ps, off);
        pd += __shfl_down_sync(0xffffffffu, pd, off);
    }
    if ((lane & 7) == 0) {
        g_als[warp * HEADS + head] = ps;
        g_ald[warp * HEADS + head] = pd;
        g_denom[warp * HEADS + head] = 0.f;
    }
}

// ---------------------------------------------------------------------------
// Pass A: softmax denominators. One thread per (virtual) edge.
// Edges e >= E are self-loops (node e - E).
// Shift-free softmax: logits are O(1) here, exp cannot overflow, and
// alpha = exp(l)/sum(exp(l)) is invariant to the max-shift in the reference.
// ---------------------------------------------------------------------------
__global__ void passA_kernel(const int* __restrict__ src, const int* __restrict__ dst,
                             int E, int Etot) {
    int e = blockIdx.x * blockDim.x + threadIdx.x;
    if (e >= Etot) return;
    int s, d;
    if (e < E) { s = src[e]; d = dst[e]; } else { s = d = e - E; }
    float4 as4 = *(const float4*)(g_als + (size_t)s * 4);
    float4 ad4 = *(const float4*)(g_ald + (size_t)d * 4);
    float4 ex;
    ex.x = __expf(lrelu(as4.x + ad4.x));
    ex.y = __expf(lrelu(as4.y + ad4.y));
    ex.z = __expf(lrelu(as4.z + ad4.z));
    ex.w = __expf(lrelu(as4.w + ad4.w));
    red_add_v4(g_denom + (size_t)d * 4, ex);
}

// ---------------------------------------------------------------------------
// Pass B layer1 (concat): one warp per edge; lane covers 8 of 256 channels.
// g_out1[dst, h, c] += alpha[h] * g_h[src, h, c]
// ---------------------------------------------------------------------------
__global__ void passB1_kernel(const int* __restrict__ src, const int* __restrict__ dst,
                              int E, int Etot) {
    int gt = blockIdx.x * blockDim.x + threadIdx.x;
    int e = gt >> 5, lane = gt & 31;
    if (e >= Etot) return;
    int s, d;
    if (e < E) { s = src[e]; d = dst[e]; } else { s = d = e - E; }
    int head = lane >> 3;
    float as_ = g_als[(size_t)s * 4 + head];
    float ad_ = g_ald[(size_t)d * 4 + head];
    float dn  = g_denom[(size_t)d * 4 + head];
    float alpha = __expf(lrelu(as_ + ad_)) / (dn + 1e-16f);
    const float4* hp = (const float4*)(g_h + (size_t)s * HC) + lane * 2;
    float4 v0 = hp[0], v1 = hp[1];
    v0.x *= alpha; v0.y *= alpha; v0.z *= alpha; v0.w *= alpha;
    v1.x *= alpha; v1.y *= alpha; v1.z *= alpha; v1.w *= alpha;
    float* op = g_out1 + (size_t)d * HC + lane * 8;
    red_add_v4(op, v0);
    red_add_v4(op + 4, v1);
}

// ---------------------------------------------------------------------------
// Pass B layer2 (mean over heads): one warp per edge; lane covers 2 of 64 ch.
// g_out2[dst, c] += 0.25 * sum_h alpha[h] * g_h[src, h, c]
// ---------------------------------------------------------------------------
__global__ void passB2_kernel(const int* __restrict__ src, const int* __restrict__ dst,
                              int E, int Etot) {
    int gt = blockIdx.x * blockDim.x + threadIdx.x;
    int e = gt >> 5, lane = gt & 31;
    if (e >= Etot) return;
    int s, d;
    if (e < E) { s = src[e]; d = dst[e]; } else { s = d = e - E; }
    float4 as4 = *(const float4*)(g_als + (size_t)s * 4);
    float4 ad4 = *(const float4*)(g_ald + (size_t)d * 4);
    float4 dn4 = *(const float4*)(g_denom + (size_t)d * 4);
    float al[4];
    al[0] = 0.25f * __expf(lrelu(as4.x + ad4.x)) / (dn4.x + 1e-16f);
    al[1] = 0.25f * __expf(lrelu(as4.y + ad4.y)) / (dn4.y + 1e-16f);
    al[2] = 0.25f * __expf(lrelu(as4.z + ad4.z)) / (dn4.z + 1e-16f);
    al[3] = 0.25f * __expf(lrelu(as4.w + ad4.w)) / (dn4.w + 1e-16f);
    const float* hrow = g_h + (size_t)s * HC;
    float2 acc = make_float2(0.f, 0.f);
#pragma unroll
    for (int hd = 0; hd < 4; hd++) {
        float2 v = *(const float2*)(hrow + hd * HID + lane * 2);
        acc.x += al[hd] * v.x;
        acc.y += al[hd] * v.y;
    }
    red_add_v2(g_out2 + (size_t)d * HID + lane * 2, acc);
}

// ---------------------------------------------------------------------------
// Init accumulation buffers with summed biases (3 relations contribute b each).
// SEL: 1 = g_out1 (C=HC), 2 = g_out2 (C=HID)
// ---------------------------------------------------------------------------
template<int SEL, int C>
__global__ void init_out_kernel(const float* __restrict__ b, int total) {
    int i = blockIdx.x * blockDim.x + threadIdx.x;
    if (i >= total) return;
    int c = i % C;
    float v = b[c] + b[C + c] + b[2 * C + c];
    if (SEL == 1) g_out1[i] = v; else g_out2[i] = v;
}

// ---------------------------------------------------------------------------
// Launcher: kernel launches ONLY (graph-capture safe, no runtime API calls)
// ---------------------------------------------------------------------------
extern "C" void kernel_launch(void* const* d_in, const int* in_sizes, int n_in,
                              void* d_out, int out_size) {
    const float* x   = (const float*)d_in[0];
    const int*   e0  = (const int*)d_in[1];
    const int*   e1  = (const int*)d_in[2];
    const int*   e2  = (const int*)d_in[3];
    const float* W1  = (const float*)d_in[4];
    const float* a1s = (const float*)d_in[5];
    const float* a1d = (const float*)d_in[6];
    const float* b1  = (const float*)d_in[7];
    const float* W2  = (const float*)d_in[8];
    const float* a2s = (const float*)d_in[9];
    const float* a2d = (const float*)d_in[10];
    const float* b2  = (const float*)d_in[11];
    const float* bl  = (const float*)d_in[13];
    const float* Wl  = (const float*)d_in[12];
    float* out = (float*)d_out;

    const int N = in_sizes[0] / IN_CH;
    const int E = in_sizes[1] / 2;

    const int* srcs[3] = {e0, e1, e2};
    const int  selfl[3] = {0, 1, 1};

    // ---------------- Layer 1 (concat) ----------------
    {
        int tot = N * HC;
        init_out_kernel<1, HC><<<(tot + 255) / 256, 256>>>(b1, tot);
    }
    for (int r = 0; r < 3; r++) {
        const int* src = srcs[r];
        const int* dst = srcs[r] + E;
        // g_h = x @ W1[r]
        {
            dim3 grid((HC + 127) / 128, (N + 127) / 128);
            sgemm_kernel<128, 128, 16, 8, 8, false, false, -1, 0><<<grid, 256>>>(
                x, W1 + (size_t)r * IN_CH * HC, nullptr, nullptr, N, HC, IN_CH);
        }
        attn_coef_kernel<<<(N + 7) / 8, 256>>>(a1s + r * HC, a1d + r * HC, N);
        int Etot = E + (selfl[r] ? N : 0);
        passA_kernel<<<(Etot + 255) / 256, 256>>>(src, dst, E, Etot);
        {
            long long th = (long long)Etot * 32;
            passB1_kernel<<<(unsigned)((th + 255) / 256), 256>>>(src, dst, E, Etot);
        }
    }

    // ---------------- Layer 2 (mean over heads) ----------------
    {
        int tot = N * HID;
        init_out_kernel<2, HID><<<(tot + 255) / 256, 256>>>(b2, tot);
    }
    for (int r = 0; r < 3; r++) {
        const int* src = srcs[r];
        const int* dst = srcs[r] + E;
        // g_h = relu(g_out1) @ W2[r]
        {
            dim3 grid((HC + 127) / 128, (N + 127) / 128);
            sgemm_kernel<128, 128, 16, 8, 8, true, false, 1, 0><<<grid, 256>>>(
                nullptr, W2 + (size_t)r * HC * HC, nullptr, nullptr, N, HC, HC);
        }
        attn_coef_kernel<<<(N + 7) / 8, 256>>>(a2s + r * HC, a2d + r * HC, N);
        int Etot = E + (selfl[r] ? N : 0);
        passA_kernel<<<(Etot + 255) / 256, 256>>>(src, dst, E, Etot);
        {
            long long th = (long long)Etot * 32;
            passB2_kernel<<<(unsigned)((th + 255) / 256), 256>>>(src, dst, E, Etot);
        }
    }

    // ---------------- Final linear: out = relu(g_out2) @ Wl + bl ----------------
    {
        dim3 grid((OUT_CH + 63) / 64, (N + 127) / 128);
        sgemm_kernel<128, 64, 16, 8, 8, true, true, 2, -1><<<grid, 128>>>(
            nullptr, Wl, out, bl, N, OUT_CH, HID);
    }
}